// round 4
// baseline (speedup 1.0000x reference)
#include <cuda_runtime.h>

#define SS 2048
#define BB 2
#define DD 768
#define HH 12
#define HD 64
#define RR 64
#define E3 (3*DD)        // 2304
#define MM (SS*BB)       // 4096
#define KA (DD+RR)       // 832
#define NHEAD (BB*HH)    // 24

// ---------------- device scratch (no allocations allowed) ----------------
__device__ float g_A1[MM*KA];            // [query | relu(lora1_down)]
__device__ float g_A2[MM*KA];            // [attn_out | relu(lora2_down)]
__device__ float g_Wqkv[E3*KA];          // [in_proj*scale1 | lora1_up*ls1]
__device__ float g_bqkv[E3];
__device__ float g_Wout[DD*KA];          // [out_w*scale2 | lora2_up*ls2]
__device__ float g_bout[DD];
__device__ float g_q[NHEAD*SS*HD];       // [B*H, S, hd], pre-scaled by hd^-0.5
__device__ float g_k[NHEAD*SS*HD];
__device__ float g_v[NHEAD*SS*HD];

// ---------------- weight prep (device code references globals: OK) ----------------
__global__ void prep_wqkv_kernel(const float* __restrict__ W, const float* __restrict__ b,
                                 const float* __restrict__ sc, const float* __restrict__ sh,
                                 const float* __restrict__ uw, const float* __restrict__ ub,
                                 const float* __restrict__ ls) {
    int idx = blockIdx.x * 256 + threadIdx.x;
    if (idx >= E3 * KA) return;
    int n = idx / KA, k = idx - n * KA;
    float l = ls[0];
    g_Wqkv[idx] = (k < DD) ? W[n * DD + k] * sc[n] : uw[n * RR + (k - DD)] * l;
    if (k == 0) g_bqkv[n] = b[n] * sc[n] + sh[n] + ub[n] * l;
}

__global__ void prep_wout_kernel(const float* __restrict__ W, const float* __restrict__ b,
                                 const float* __restrict__ sc, const float* __restrict__ sh,
                                 const float* __restrict__ uw, const float* __restrict__ ub,
                                 const float* __restrict__ ls) {
    int idx = blockIdx.x * 256 + threadIdx.x;
    if (idx >= DD * KA) return;
    int n = idx / KA, k = idx - n * KA;
    float l = ls[0];
    g_Wout[idx] = (k < DD) ? W[n * DD + k] * sc[n] : uw[n * RR + (k - DD)] * l;
    if (k == 0) g_bout[n] = b[n] * sc[n] + sh[n] + ub[n] * l;
}

__global__ void pack_query_kernel(const float* __restrict__ q) {
    int idx = blockIdx.x * 256 + threadIdx.x;
    if (idx >= MM * DD) return;
    int m = idx / DD, d = idx - m * DD;
    g_A1[(size_t)m * KA + d] = q[idx];
}

// ---------------- 64x64 tiled GEMM: C[m,n] = sum_k A[m,k]*W[n,k] + bias ----------
// MODE 1: lora1-down  A=arg(query,lda 768) W=arg bias=arg   -> relu into g_A1[:,768:]
// MODE 2: qkv         A=g_A1 W=g_Wqkv bias=g_bqkv (K=832)   -> scatter g_q/g_k/g_v
// MODE 3: lora2-down  A=g_A2 W=arg bias=arg                 -> relu into g_A2[:,768:]
//                     (reads cols [0,768), writes cols [768,832): disjoint, no race)
// MODE 0: out-proj    A=g_A2 W=g_Wout bias=g_bout (K=832)   -> arg C (d_out, ld 768)
template<int MODE>
__global__ __launch_bounds__(256) void gemm64_kernel(
    const float* __restrict__ Aarg,
    const float* __restrict__ Warg,
    const float* __restrict__ barg,
    float* __restrict__ Carg)
{
    const float* A; const float* W; const float* bias;
    int lda, ldw, K;
    if (MODE == 1)      { A = Aarg;  lda = DD; W = Warg;   ldw = DD; bias = barg;   K = DD; }
    else if (MODE == 2) { A = g_A1;  lda = KA; W = g_Wqkv; ldw = KA; bias = g_bqkv; K = KA; }
    else if (MODE == 3) { A = g_A2;  lda = KA; W = Warg;   ldw = DD; bias = barg;   K = DD; }
    else                { A = g_A2;  lda = KA; W = g_Wout; ldw = KA; bias = g_bout; K = KA; }

    __shared__ float As[16][65];
    __shared__ float Bs[16][65];
    int tx = threadIdx.x, ty = threadIdx.y;
    int t  = ty * 16 + tx;
    int m0 = blockIdx.y * 64, n0 = blockIdx.x * 64;
    int ar = t >> 4, ak = t & 15;

    const float* Ap = A + (size_t)(m0 + ar) * lda + ak;
    const float* Wp = W + (size_t)(n0 + ar) * ldw + ak;

    float acc[4][4];
#pragma unroll
    for (int i = 0; i < 4; i++)
#pragma unroll
        for (int j = 0; j < 4; j++) acc[i][j] = 0.f;

    for (int k0 = 0; k0 < K; k0 += 16) {
#pragma unroll
        for (int p = 0; p < 4; p++) {
            As[ak][ar + 16 * p] = Ap[(size_t)(16 * p) * lda + k0];
            Bs[ak][ar + 16 * p] = Wp[(size_t)(16 * p) * ldw + k0];
        }
        __syncthreads();
#pragma unroll
        for (int kk = 0; kk < 16; kk++) {
            float a[4], bf[4];
#pragma unroll
            for (int i = 0; i < 4; i++) a[i]  = As[kk][ty + 16 * i];
#pragma unroll
            for (int j = 0; j < 4; j++) bf[j] = Bs[kk][tx + 16 * j];
#pragma unroll
            for (int i = 0; i < 4; i++)
#pragma unroll
                for (int j = 0; j < 4; j++)
                    acc[i][j] = fmaf(a[i], bf[j], acc[i][j]);
        }
        __syncthreads();
    }

#pragma unroll
    for (int i = 0; i < 4; i++) {
        int m = m0 + ty + 16 * i;
#pragma unroll
        for (int j = 0; j < 4; j++) {
            int n = n0 + tx + 16 * j;
            float v = acc[i][j] + bias[n];
            if (MODE == 0) {
                Carg[(size_t)m * DD + n] = v;
            } else if (MODE == 1) {
                g_A1[(size_t)m * KA + DD + n] = fmaxf(v, 0.f);
            } else if (MODE == 3) {
                g_A2[(size_t)m * KA + DD + n] = fmaxf(v, 0.f);
            } else {  // MODE 2: scatter into q/k/v head layout
                int part = n / DD, e = n - part * DD;
                int h = e >> 6, cc = e & 63;
                int s = m / BB, b = m - s * BB;
                float* dst = (part == 0) ? g_q : (part == 1) ? g_k : g_v;
                if (part == 0) v *= 0.125f;   // hd^-0.5
                dst[((size_t)(b * HH + h) * SS + s) * HD + cc] = v;
            }
        }
    }
}

// ---------------- flash attention: one block = (head, 64 q-rows) ----------------
__global__ __launch_bounds__(256) void attn_kernel() {
    __shared__ float Qs[64 * 64];   // plain, reads are broadcast
    __shared__ float Ks[64 * 64];   // rotated swizzle for QK^T reads; reused for P
    __shared__ float Vs[64 * 64];   // plain, reads are stride-1
    // 48 KB static shared total: exactly at the static smem limit.

    int head = blockIdx.x;
    int q0   = blockIdx.y * 64;
    int tx = threadIdx.x, ty = threadIdx.y;
    int t = ty * 16 + tx;

    const float* qb = g_q + ((size_t)head * SS + q0) * HD;
    for (int idx = t; idx < 4096; idx += 256) Qs[idx] = qb[idx];

    float o[4][4];
    float mrow[4], lrow[4];
#pragma unroll
    for (int i = 0; i < 4; i++) {
        mrow[i] = __int_as_float(0xff800000);  // -inf
        lrow[i] = 0.f;
#pragma unroll
        for (int j = 0; j < 4; j++) o[i][j] = 0.f;
    }

    for (int kv0 = 0; kv0 < SS; kv0 += 64) {
        const float* kb = g_k + ((size_t)head * SS + kv0) * HD;
        const float* vb = g_v + ((size_t)head * SS + kv0) * HD;
        for (int idx = t; idx < 4096; idx += 256) {
            int r = idx >> 6, c = idx & 63;
            Ks[r * 64 + ((c + r) & 63)] = kb[idx];   // rotate-swizzled
            Vs[idx] = vb[idx];
        }
        __syncthreads();

        // S = Q @ K^T  (rows ty+16i, cols tx+16j)
        float sc[4][4];
#pragma unroll
        for (int i = 0; i < 4; i++)
#pragma unroll
            for (int j = 0; j < 4; j++) sc[i][j] = 0.f;
        for (int h = 0; h < HD; h++) {
            float a[4], bf[4];
#pragma unroll
            for (int i = 0; i < 4; i++) a[i] = Qs[(ty + 16 * i) * 64 + h];
#pragma unroll
            for (int j = 0; j < 4; j++) {
                int col = tx + 16 * j;
                bf[j] = Ks[col * 64 + ((h + col) & 63)];
            }
#pragma unroll
            for (int i = 0; i < 4; i++)
#pragma unroll
                for (int j = 0; j < 4; j++)
                    sc[i][j] = fmaf(a[i], bf[j], sc[i][j]);
        }

        // online softmax update (row spread across the 16 tx lanes of a half-warp;
        // xor offsets 1..8 never cross the 16-lane boundary, ty is uniform per half)
#pragma unroll
        for (int i = 0; i < 4; i++) {
            float mx = fmaxf(fmaxf(sc[i][0], sc[i][1]), fmaxf(sc[i][2], sc[i][3]));
#pragma unroll
            for (int off = 1; off < 16; off <<= 1)
                mx = fmaxf(mx, __shfl_xor_sync(0xffffffffu, mx, off));
            float mnew = fmaxf(mrow[i], mx);
            float ps = 0.f;
#pragma unroll
            for (int j = 0; j < 4; j++) {
                sc[i][j] = __expf(sc[i][j] - mnew);
                ps += sc[i][j];
            }
#pragma unroll
            for (int off = 1; off < 16; off <<= 1)
                ps += __shfl_xor_sync(0xffffffffu, ps, off);
            float alpha = __expf(mrow[i] - mnew);
            lrow[i] = lrow[i] * alpha + ps;
            mrow[i] = mnew;
#pragma unroll
            for (int j = 0; j < 4; j++) o[i][j] *= alpha;
        }

        __syncthreads();                       // all K reads done
#pragma unroll
        for (int i = 0; i < 4; i++)
#pragma unroll
            for (int j = 0; j < 4; j++)
                Ks[(ty + 16 * i) * 64 + tx + 16 * j] = sc[i][j];  // P, plain layout
        __syncthreads();

        // O += P @ V
        for (int kv = 0; kv < 64; kv++) {
            float a[4], bf[4];
#pragma unroll
            for (int i = 0; i < 4; i++) a[i]  = Ks[(ty + 16 * i) * 64 + kv];
#pragma unroll
            for (int j = 0; j < 4; j++) bf[j] = Vs[kv * 64 + tx + 16 * j];
#pragma unroll
            for (int i = 0; i < 4; i++)
#pragma unroll
                for (int j = 0; j < 4; j++)
                    o[i][j] = fmaf(a[i], bf[j], o[i][j]);
        }
        __syncthreads();
    }

    // write attn output into g_A2 cols [0,768): rows m = s*B+b
    int b  = head / HH, hh = head - b * HH;
#pragma unroll
    for (int i = 0; i < 4; i++) {
        float inv = 1.f / lrow[i];
        int s = q0 + ty + 16 * i;
        size_t base = (size_t)(s * BB + b) * KA + hh * HD;
#pragma unroll
        for (int j = 0; j < 4; j++)
            g_A2[base + tx + 16 * j] = o[i][j] * inv;
    }
}

// ---------------- launch ----------------
extern "C" void kernel_launch(void* const* d_in, const int* in_sizes, int n_in,
                              void* d_out, int out_size) {
    const float* query   = (const float*)d_in[0];
    // d_in[1] key, d_in[2] value: unused by reference (self-attn on query)
    const float* ipw     = (const float*)d_in[3];
    const float* ipb     = (const float*)d_in[4];
    const float* sc1     = (const float*)d_in[5];
    const float* sh1     = (const float*)d_in[6];
    const float* l1dw    = (const float*)d_in[7];
    const float* l1db    = (const float*)d_in[8];
    const float* l1uw    = (const float*)d_in[9];
    const float* l1ub    = (const float*)d_in[10];
    const float* l1s     = (const float*)d_in[11];
    const float* outw    = (const float*)d_in[12];
    const float* outb    = (const float*)d_in[13];
    const float* sc2     = (const float*)d_in[14];
    const float* sh2     = (const float*)d_in[15];
    const float* l2dw    = (const float*)d_in[16];
    const float* l2db    = (const float*)d_in[17];
    const float* l2uw    = (const float*)d_in[18];
    const float* l2ub    = (const float*)d_in[19];
    const float* l2s     = (const float*)d_in[20];
    float* out = (float*)d_out;

    dim3 blk(16, 16);

    prep_wqkv_kernel<<<(E3 * KA + 255) / 256, 256>>>(ipw, ipb, sc1, sh1, l1uw, l1ub, l1s);
    prep_wout_kernel<<<(DD * KA + 255) / 256, 256>>>(outw, outb, sc2, sh2, l2uw, l2ub, l2s);
    pack_query_kernel<<<(MM * DD + 255) / 256, 256>>>(query);

    // lora1 down: relu(query @ dw^T + db) -> g_A1 cols [768,832)
    gemm64_kernel<1><<<dim3(1, MM / 64), blk>>>(query, l1dw, l1db, nullptr);
    // fused QKV: g_A1[4096x832] @ g_Wqkv^T -> scatter to g_q/g_k/g_v
    gemm64_kernel<2><<<dim3(E3 / 64, MM / 64), blk>>>(nullptr, nullptr, nullptr, nullptr);
    // attention
    attn_kernel<<<dim3(NHEAD, SS / 64), blk>>>();
    // lora2 down: relu(g_A2[:, :768] @ dw2^T + db2) -> g_A2 cols [768,832)
    gemm64_kernel<3><<<dim3(1, MM / 64), blk>>>(nullptr, l2dw, l2db, nullptr);
    // fused output projection -> d_out [S,B,D]
    gemm64_kernel<0><<<dim3(DD / 64, MM / 64), blk>>>(nullptr, nullptr, nullptr, out);
}

// round 6
// speedup vs baseline: 1.4816x; 1.4816x over previous
#include <cuda_runtime.h>

#define SS 2048
#define BB 2
#define DD 768
#define HH 12
#define HD 64
#define RR 64
#define E3 (3*DD)        // 2304
#define MM (SS*BB)       // 4096
#define KA (DD+RR)       // 832
#define NHEAD (BB*HH)    // 24

// ---------------- device scratch (16B aligned for float4) ----------------
__device__ __align__(16) float g_A1[MM*KA];     // [query | relu(lora1_down)]
__device__ __align__(16) float g_A2[MM*KA];     // [attn_out | relu(lora2_down)]
__device__ __align__(16) float g_Wqkv[E3*KA];   // [in_proj*scale1 | lora1_up*ls1]
__device__ __align__(16) float g_bqkv[E3];
__device__ __align__(16) float g_Wout[DD*KA];   // [out_w*scale2 | lora2_up*ls2]
__device__ __align__(16) float g_bout[DD];
__device__ __align__(16) float g_q[NHEAD*SS*HD]; // [B*H, S, hd], pre-scaled
__device__ __align__(16) float g_k[NHEAD*SS*HD];
__device__ __align__(16) float g_v[NHEAD*SS*HD];

// ---------------- weight prep ----------------
__global__ void prep_wqkv_kernel(const float* __restrict__ W, const float* __restrict__ b,
                                 const float* __restrict__ sc, const float* __restrict__ sh,
                                 const float* __restrict__ uw, const float* __restrict__ ub,
                                 const float* __restrict__ ls) {
    int idx = blockIdx.x * 256 + threadIdx.x;
    if (idx >= E3 * KA) return;
    int n = idx / KA, k = idx - n * KA;
    float l = ls[0];
    g_Wqkv[idx] = (k < DD) ? W[n * DD + k] * sc[n] : uw[n * RR + (k - DD)] * l;
    if (k == 0) g_bqkv[n] = b[n] * sc[n] + sh[n] + ub[n] * l;
}

__global__ void prep_wout_kernel(const float* __restrict__ W, const float* __restrict__ b,
                                 const float* __restrict__ sc, const float* __restrict__ sh,
                                 const float* __restrict__ uw, const float* __restrict__ ub,
                                 const float* __restrict__ ls) {
    int idx = blockIdx.x * 256 + threadIdx.x;
    if (idx >= DD * KA) return;
    int n = idx / KA, k = idx - n * KA;
    float l = ls[0];
    g_Wout[idx] = (k < DD) ? W[n * DD + k] * sc[n] : uw[n * RR + (k - DD)] * l;
    if (k == 0) g_bout[n] = b[n] * sc[n] + sh[n] + ub[n] * l;
}

__global__ void pack_query_kernel(const float* __restrict__ q) {
    int idx = blockIdx.x * 256 + threadIdx.x;      // float4 index
    if (idx >= MM * DD / 4) return;
    int m = idx / (DD / 4), d4 = idx - m * (DD / 4);
    *(float4*)&g_A1[(size_t)m * KA + d4 * 4] = *(const float4*)(q + (size_t)m * DD + d4 * 4);
}

// ---------------- small 64x64 GEMM for lora downs (N=64) ----------------
// MODE 1: A=arg(query,lda 768) -> relu into g_A1[:,768:]
// MODE 3: A=g_A2 (lda KA)      -> relu into g_A2[:,768:]  (cols disjoint, no race)
template<int MODE>
__global__ __launch_bounds__(256) void gemm64_kernel(
    const float* __restrict__ Aarg,
    const float* __restrict__ Warg,
    const float* __restrict__ barg)
{
    const float* A = (MODE == 1) ? Aarg : g_A2;
    const int lda  = (MODE == 1) ? DD : KA;
    const float* W = Warg; const float* bias = barg;
    const int K = DD;

    __shared__ float As[16][65];
    __shared__ float Bs[16][65];
    int tx = threadIdx.x & 15, ty = threadIdx.x >> 4;
    int t  = threadIdx.x;
    int m0 = blockIdx.y * 64;
    int ar = t >> 4, ak = t & 15;

    const float* Ap = A + (size_t)(m0 + ar) * lda + ak;
    const float* Wp = W + (size_t)ar * DD + ak;

    float acc[4][4];
#pragma unroll
    for (int i = 0; i < 4; i++)
#pragma unroll
        for (int j = 0; j < 4; j++) acc[i][j] = 0.f;

    for (int k0 = 0; k0 < K; k0 += 16) {
#pragma unroll
        for (int p = 0; p < 4; p++) {
            As[ak][ar + 16 * p] = Ap[(size_t)(16 * p) * lda + k0];
            Bs[ak][ar + 16 * p] = Wp[(size_t)(16 * p) * DD + k0];
        }
        __syncthreads();
#pragma unroll
        for (int kk = 0; kk < 16; kk++) {
            float a[4], bf[4];
#pragma unroll
            for (int i = 0; i < 4; i++) a[i]  = As[kk][ty + 16 * i];
#pragma unroll
            for (int j = 0; j < 4; j++) bf[j] = Bs[kk][tx + 16 * j];
#pragma unroll
            for (int i = 0; i < 4; i++)
#pragma unroll
                for (int j = 0; j < 4; j++)
                    acc[i][j] = fmaf(a[i], bf[j], acc[i][j]);
        }
        __syncthreads();
    }

#pragma unroll
    for (int i = 0; i < 4; i++) {
        int m = m0 + ty + 16 * i;
#pragma unroll
        for (int j = 0; j < 4; j++) {
            int n = tx + 16 * j;
            float v = fmaxf(acc[i][j] + bias[n], 0.f);
            if (MODE == 1) g_A1[(size_t)m * KA + DD + n] = v;
            else           g_A2[(size_t)m * KA + DD + n] = v;
        }
    }
}

// ---------------- big GEMM: 128x128x16 double-buffered, 8x8 microtile ----------
// MODE 2: A=g_A1, W=g_Wqkv, bias=g_bqkv -> scatter to g_q/g_k/g_v
// MODE 0: A=g_A2, W=g_Wout, bias=g_bout -> Carg (d_out, ld 768)
template<int MODE>
__global__ __launch_bounds__(256) void gemm128_kernel(float* __restrict__ Carg)
{
    const float* A    = (MODE == 2) ? g_A1   : g_A2;
    const float* W    = (MODE == 2) ? g_Wqkv : g_Wout;
    const float* bias = (MODE == 2) ? g_bqkv : g_bout;
    const int NCHUNK  = KA / 16;   // 52

    __shared__ float As[2][16][128];
    __shared__ float Bs[2][16][128];

    int t  = threadIdx.x;
    int tx = t & 15, ty = t >> 4;
    int m0 = blockIdx.y * 128, n0 = blockIdx.x * 128;

    int lrow = t >> 1;              // 0..127
    int lk   = (t & 1) * 8;         // 0 or 8

    const float* Ap = A + (size_t)(m0 + lrow) * KA + lk;
    const float* Wp = W + (size_t)(n0 + lrow) * KA + lk;

    float4 ra0, ra1, rb0, rb1;
    ra0 = *(const float4*)(Ap + 0);  ra1 = *(const float4*)(Ap + 4);
    rb0 = *(const float4*)(Wp + 0);  rb1 = *(const float4*)(Wp + 4);
#pragma unroll
    for (int j = 0; j < 4; j++) {
        As[0][lk + j][lrow]     = ((const float*)&ra0)[j];
        As[0][lk + 4 + j][lrow] = ((const float*)&ra1)[j];
        Bs[0][lk + j][lrow]     = ((const float*)&rb0)[j];
        Bs[0][lk + 4 + j][lrow] = ((const float*)&rb1)[j];
    }
    __syncthreads();

    float acc[8][8];
#pragma unroll
    for (int i = 0; i < 8; i++)
#pragma unroll
        for (int j = 0; j < 8; j++) acc[i][j] = 0.f;

    for (int c = 0; c < NCHUNK; c++) {
        int cur = c & 1;
        if (c + 1 < NCHUNK) {
            const float* Ap2 = Ap + (c + 1) * 16;
            const float* Wp2 = Wp + (c + 1) * 16;
            ra0 = *(const float4*)(Ap2 + 0);  ra1 = *(const float4*)(Ap2 + 4);
            rb0 = *(const float4*)(Wp2 + 0);  rb1 = *(const float4*)(Wp2 + 4);
        }
#pragma unroll
        for (int kk = 0; kk < 16; kk++) {
            float4 a0 = *(const float4*)&As[cur][kk][ty * 8];
            float4 a1 = *(const float4*)&As[cur][kk][ty * 8 + 4];
            float4 b0 = *(const float4*)&Bs[cur][kk][tx * 8];
            float4 b1 = *(const float4*)&Bs[cur][kk][tx * 8 + 4];
            const float* av = (const float*)&a0;
            const float* bv = (const float*)&b0;
#pragma unroll
            for (int i = 0; i < 4; i++) {
                float ai = av[i];
#pragma unroll
                for (int j = 0; j < 4; j++) {
                    acc[i][j]     = fmaf(ai, bv[j], acc[i][j]);
                    acc[i][j + 4] = fmaf(ai, ((const float*)&b1)[j], acc[i][j + 4]);
                }
            }
#pragma unroll
            for (int i = 0; i < 4; i++) {
                float ai = ((const float*)&a1)[i];
#pragma unroll
                for (int j = 0; j < 4; j++) {
                    acc[i + 4][j]     = fmaf(ai, bv[j], acc[i + 4][j]);
                    acc[i + 4][j + 4] = fmaf(ai, ((const float*)&b1)[j], acc[i + 4][j + 4]);
                }
            }
        }
        if (c + 1 < NCHUNK) {
            int nxt = cur ^ 1;
#pragma unroll
            for (int j = 0; j < 4; j++) {
                As[nxt][lk + j][lrow]     = ((const float*)&ra0)[j];
                As[nxt][lk + 4 + j][lrow] = ((const float*)&ra1)[j];
                Bs[nxt][lk + j][lrow]     = ((const float*)&rb0)[j];
                Bs[nxt][lk + 4 + j][lrow] = ((const float*)&rb1)[j];
            }
            __syncthreads();
        }
    }

    // epilogue
    float bb[8];
#pragma unroll
    for (int j = 0; j < 8; j++) bb[j] = bias[n0 + tx * 8 + j];

    if (MODE == 0) {
#pragma unroll
        for (int i = 0; i < 8; i++) {
            int m = m0 + ty * 8 + i;
            float4 v0 = make_float4(acc[i][0] + bb[0], acc[i][1] + bb[1],
                                    acc[i][2] + bb[2], acc[i][3] + bb[3]);
            float4 v1 = make_float4(acc[i][4] + bb[4], acc[i][5] + bb[5],
                                    acc[i][6] + bb[6], acc[i][7] + bb[7]);
            *(float4*)(Carg + (size_t)m * DD + n0 + tx * 8)     = v0;
            *(float4*)(Carg + (size_t)m * DD + n0 + tx * 8 + 4) = v1;
        }
    } else {
        int ncol = n0 + tx * 8;
        int part = ncol / DD;
        int e    = ncol - part * DD;
        int h    = e >> 6, cc = e & 63;
        float* dst = (part == 0) ? g_q : (part == 1) ? g_k : g_v;
        float scl  = (part == 0) ? 0.125f : 1.f;     // hd^-0.5 on q
#pragma unroll
        for (int i = 0; i < 8; i++) {
            int m = m0 + ty * 8 + i;
            int s = m >> 1, b = m & 1;
            float* p = dst + ((size_t)(b * HH + h) * SS + s) * HD + cc;
            float4 v0 = make_float4((acc[i][0] + bb[0]) * scl, (acc[i][1] + bb[1]) * scl,
                                    (acc[i][2] + bb[2]) * scl, (acc[i][3] + bb[3]) * scl);
            float4 v1 = make_float4((acc[i][4] + bb[4]) * scl, (acc[i][5] + bb[5]) * scl,
                                    (acc[i][6] + bb[6]) * scl, (acc[i][7] + bb[7]) * scl);
            *(float4*)(p)     = v0;
            *(float4*)(p + 4) = v1;
        }
    }
}

// ---------------- flash attention: block = (head, 64 q-rows), 4x4 micro, f4 ----
__global__ __launch_bounds__(256) void attn_kernel() {
    __shared__ float QsT[64 * 64];   // [h][r]
    __shared__ float KsT[64 * 64];   // [h][c]; reused as P [r][kv]
    __shared__ float Vs[64 * 64];    // [kv][c]

    int head = blockIdx.x;
    int q0   = blockIdx.y * 64;
    int t  = threadIdx.x;
    int tx = t & 15, ty = t >> 4;

    // load Q transposed: QsT[h][r] = q[r][h]
    {
        int r = t >> 2, cq0 = t & 3;
        const float* qb = g_q + ((size_t)head * SS + q0 + r) * HD;
#pragma unroll
        for (int i = 0; i < 4; i++) {
            int hq = cq0 + 4 * i;
            float4 v = *(const float4*)(qb + hq * 4);
#pragma unroll
            for (int j = 0; j < 4; j++)
                QsT[(hq * 4 + j) * 64 + r] = ((const float*)&v)[j];
        }
    }

    float o[4][4], mrow[4], lrow[4];
#pragma unroll
    for (int i = 0; i < 4; i++) {
        mrow[i] = __int_as_float(0xff800000);
        lrow[i] = 0.f;
#pragma unroll
        for (int j = 0; j < 4; j++) o[i][j] = 0.f;
    }

    for (int kv0 = 0; kv0 < SS; kv0 += 64) {
        __syncthreads();   // prev PV done with Ps/Vs; also orders Q stores (1st iter)
        {
            int r = t >> 2, cq0 = t & 3;
            const float* kb = g_k + ((size_t)head * SS + kv0 + r) * HD;
            const float* vb = g_v + ((size_t)head * SS + kv0 + r) * HD;
#pragma unroll
            for (int i = 0; i < 4; i++) {
                int hq = cq0 + 4 * i;
                float4 kv4 = *(const float4*)(kb + hq * 4);
#pragma unroll
                for (int j = 0; j < 4; j++)
                    KsT[(hq * 4 + j) * 64 + r] = ((const float*)&kv4)[j];
                *(float4*)&Vs[r * 64 + hq * 4] = *(const float4*)(vb + hq * 4);
            }
        }
        __syncthreads();

        // S = Q^T-layout K: sc[i][j] = sum_h QsT[h][ty*4+i] * KsT[h][tx*4+j]
        float sc[4][4];
#pragma unroll
        for (int i = 0; i < 4; i++)
#pragma unroll
            for (int j = 0; j < 4; j++) sc[i][j] = 0.f;
        {
            const float* qr = QsT + ty * 4;
            const float* kr = KsT + tx * 4;
#pragma unroll 1
            for (int h0 = 0; h0 < 4; h0++) {
#pragma unroll
                for (int u = 0; u < 16; u++) {
                    float4 a4 = *(const float4*)(qr + u * 64);
                    float4 b4 = *(const float4*)(kr + u * 64);
                    const float* av = (const float*)&a4;
                    const float* bv = (const float*)&b4;
#pragma unroll
                    for (int i = 0; i < 4; i++)
#pragma unroll
                        for (int j = 0; j < 4; j++)
                            sc[i][j] = fmaf(av[i], bv[j], sc[i][j]);
                }
                qr += 1024; kr += 1024;
            }
        }

        // online softmax (rows spread across 16 tx lanes; xor 1..8 stays in half-warp)
#pragma unroll
        for (int i = 0; i < 4; i++) {
            float mx = fmaxf(fmaxf(sc[i][0], sc[i][1]), fmaxf(sc[i][2], sc[i][3]));
#pragma unroll
            for (int off = 1; off < 16; off <<= 1)
                mx = fmaxf(mx, __shfl_xor_sync(0xffffffffu, mx, off));
            float mnew = fmaxf(mrow[i], mx);
            float ps = 0.f;
#pragma unroll
            for (int j = 0; j < 4; j++) {
                sc[i][j] = __expf(sc[i][j] - mnew);
                ps += sc[i][j];
            }
#pragma unroll
            for (int off = 1; off < 16; off <<= 1)
                ps += __shfl_xor_sync(0xffffffffu, ps, off);
            float alpha = __expf(mrow[i] - mnew);
            lrow[i] = lrow[i] * alpha + ps;
            mrow[i] = mnew;
#pragma unroll
            for (int j = 0; j < 4; j++) o[i][j] *= alpha;
        }

        __syncthreads();   // all KsT reads done
        // P into KsT buffer as Ps[r][kv]
#pragma unroll
        for (int i = 0; i < 4; i++)
            *(float4*)&KsT[(ty * 4 + i) * 64 + tx * 4] =
                make_float4(sc[i][0], sc[i][1], sc[i][2], sc[i][3]);
        __syncthreads();

        // O += P @ V  (4 kv per step)
        {
            const float* pr = KsT + ty * 4 * 64;   // row base for i=0
            const float* vr = Vs + tx * 4;
#pragma unroll
            for (int kq = 0; kq < 16; kq++) {
                float4 a4[4], b4[4];
#pragma unroll
                for (int i = 0; i < 4; i++)
                    a4[i] = *(const float4*)(pr + i * 64 + kq * 4);
#pragma unroll
                for (int k = 0; k < 4; k++)
                    b4[k] = *(const float4*)(vr + (kq * 4 + k) * 64);
#pragma unroll
                for (int i = 0; i < 4; i++) {
                    const float* av = (const float*)&a4[i];
#pragma unroll
                    for (int k = 0; k < 4; k++) {
                        const float* bv = (const float*)&b4[k];
#pragma unroll
                        for (int j = 0; j < 4; j++)
                            o[i][j] = fmaf(av[k], bv[j], o[i][j]);
                    }
                }
            }
        }
    }

    // write attn output into g_A2 cols [0,768): rows m = s*B+b
    int b  = head / HH, hh = head - b * HH;
#pragma unroll
    for (int i = 0; i < 4; i++) {
        float inv = 1.f / lrow[i];
        int s = q0 + ty * 4 + i;
        *(float4*)&g_A2[(size_t)(s * BB + b) * KA + hh * HD + tx * 4] =
            make_float4(o[i][0] * inv, o[i][1] * inv, o[i][2] * inv, o[i][3] * inv);
    }
}

// ---------------- launch ----------------
extern "C" void kernel_launch(void* const* d_in, const int* in_sizes, int n_in,
                              void* d_out, int out_size) {
    const float* query   = (const float*)d_in[0];
    // d_in[1] key, d_in[2] value: unused by reference (self-attn on query)
    const float* ipw     = (const float*)d_in[3];
    const float* ipb     = (const float*)d_in[4];
    const float* sc1     = (const float*)d_in[5];
    const float* sh1     = (const float*)d_in[6];
    const float* l1dw    = (const float*)d_in[7];
    const float* l1db    = (const float*)d_in[8];
    const float* l1uw    = (const float*)d_in[9];
    const float* l1ub    = (const float*)d_in[10];
    const float* l1s     = (const float*)d_in[11];
    const float* outw    = (const float*)d_in[12];
    const float* outb    = (const float*)d_in[13];
    const float* sc2     = (const float*)d_in[14];
    const float* sh2     = (const float*)d_in[15];
    const float* l2dw    = (const float*)d_in[16];
    const float* l2db    = (const float*)d_in[17];
    const float* l2uw    = (const float*)d_in[18];
    const float* l2ub    = (const float*)d_in[19];
    const float* l2s     = (const float*)d_in[20];
    float* out = (float*)d_out;

    prep_wqkv_kernel<<<(E3 * KA + 255) / 256, 256>>>(ipw, ipb, sc1, sh1, l1uw, l1ub, l1s);
    prep_wout_kernel<<<(DD * KA + 255) / 256, 256>>>(outw, outb, sc2, sh2, l2uw, l2ub, l2s);
    pack_query_kernel<<<(MM * DD / 4 + 255) / 256, 256>>>(query);

    // lora1 down -> g_A1 cols [768,832)
    gemm64_kernel<1><<<dim3(1, MM / 64), 256>>>(query, l1dw, l1db);
    // fused QKV: g_A1[4096x832] @ g_Wqkv^T -> scatter to g_q/g_k/g_v
    gemm128_kernel<2><<<dim3(E3 / 128, MM / 128), 256>>>(nullptr);
    // attention -> g_A2 cols [0,768)
    attn_kernel<<<dim3(NHEAD, SS / 64), 256>>>();
    // lora2 down -> g_A2 cols [768,832)
    gemm64_kernel<3><<<dim3(1, MM / 64), 256>>>(nullptr, l2dw, l2db);
    // fused output projection -> d_out [S,B,D]
    gemm128_kernel<0><<<dim3(DD / 128, MM / 128), 256>>>(out);
}